// round 4
// baseline (speedup 1.0000x reference)
#include <cuda_runtime.h>
#include <stdint.h>

#define NEGF (-1e30f)

constexpr int T = 1024;
constexpr int B = 32;
constexpr int C = 96;
constexpr int W = 16;   // beam width
constexpr int P = 4;    // top paths
constexpr int S = 20;   // top lp columns kept per (b,t)

// scratch: per (b,t) the top-S non-blank lp columns as packed keys (ord(lp)<<7 | (127-c))
__device__ unsigned long long g_sorted[(size_t)B * T * S];

// ---------- key helpers ----------
__device__ __forceinline__ unsigned ford(float f) {
    unsigned u = __float_as_uint(f);
    return (u & 0x80000000u) ? ~u : (u | 0x80000000u);
}
__device__ __forceinline__ float funord(unsigned ord) {
    unsigned u = (ord & 0x80000000u) ? (ord ^ 0x80000000u) : ~ord;
    return __uint_as_float(u);
}
// candidate key: larger score wins; ties -> lower global index wins (matches jax.lax.top_k)
__device__ __forceinline__ unsigned long long make_key(float f, int idx) {
    return ((unsigned long long)ford(f) << 11) | (unsigned long long)(2047 - idx);
}
__device__ __forceinline__ int key_idx(unsigned long long k) { return 2047 - (int)(k & 2047ULL); }
__device__ __forceinline__ float key_score(unsigned long long k) { return funord((unsigned)(k >> 11)); }

// logaddexp, same formula as jnp.logaddexp
__device__ __forceinline__ float lae(float a, float b) {
    float m = fmaxf(a, b);
    float d = fabsf(a - b);
    return m + log1pf(expf(-d));
}
__device__ __forceinline__ unsigned long long warp_max(unsigned long long v) {
    #pragma unroll
    for (int o = 16; o; o >>= 1) {
        unsigned long long w = __shfl_xor_sync(0xffffffffu, v, o);
        v = (w > v) ? w : v;
    }
    return v;
}

// ============================================================================
// Kernel 1: per-(b,t) sort of non-blank lp columns, keep top-S. One warp each.
// Layout: element e = r*32 + lane  (e == column c initially).
// ============================================================================
__global__ __launch_bounds__(256)
void presort_kernel(const float* __restrict__ data)   // [T, B, C]
{
    int warp = (blockIdx.x * blockDim.x + threadIdx.x) >> 5;
    if (warp >= B * T) return;
    int b = warp / T, t = warp - b * T;
    int lane = threadIdx.x & 31;

    const float* row = data + ((size_t)t * B + b) * C;
    unsigned long long k[4];
    #pragma unroll
    for (int r = 0; r < 4; ++r) {
        int c = r * 32 + lane;
        if (c >= 1 && c < C)
            k[r] = ((unsigned long long)ford(row[c]) << 7) | (unsigned long long)(127 - c);
        else
            k[r] = 0ULL;   // blank + padding sink to bottom
    }

    // bitonic sort of 128 keys, descending
    #pragma unroll
    for (int k2 = 2; k2 <= 128; k2 <<= 1) {
        #pragma unroll
        for (int j = 64; j > 0; j >>= 1) {
            if (j >= k2) continue;
            if (j >= 32) {                       // register-local compare-exchange
                int rj = j >> 5;
                #pragma unroll
                for (int r = 0; r < 4; ++r) {
                    if ((r & rj) == 0) {
                        int pr = r | rj;
                        bool desc = (((r * 32) & k2) == 0);   // lane bits don't reach k2>=64
                        unsigned long long a = k[r], c2 = k[pr];
                        unsigned long long mx = a > c2 ? a : c2;
                        unsigned long long mn = a > c2 ? c2 : a;
                        k[r]  = desc ? mx : mn;
                        k[pr] = desc ? mn : mx;
                    }
                }
            } else {                              // cross-lane compare-exchange
                #pragma unroll
                for (int r = 0; r < 4; ++r) {
                    unsigned long long o = __shfl_xor_sync(0xffffffffu, k[r], j);
                    int e = r * 32 + lane;
                    bool takemax = ((e & k2) == 0) == ((lane & j) == 0);
                    bool bigger  = k[r] > o;
                    k[r] = (takemax == bigger) ? k[r] : o;
                }
            }
        }
    }
    // sorted desc: elements 0..31 live in k[0] at lane==e
    if (lane < S)
        g_sorted[((size_t)b * T + t) * S + lane] = k[0];
}

// ============================================================================
// Kernel 2: sequential beam search, one CTA per batch element, warp w = beam w.
// ============================================================================
__global__ __launch_bounds__(512, 1)
void ctc_beam_kernel(const float* __restrict__ data,      // [T, B, C] log-probs
                     const int*   __restrict__ data_len,  // [B]
                     float*       __restrict__ out)       // [B*P] + [B*P] + [B*P*T]
{
    const int b    = blockIdx.x;
    const int tid  = threadIdx.x;
    const int lane = tid & 31;
    const int wid  = tid >> 5;
    const int len  = data_len[b];

    __shared__ float sh_lp[2][C];
    __shared__ unsigned long long sh_srt[2][S];
    __shared__ float s_pb[2][W], s_pnb[2][W];
    __shared__ int   s_ln[2][W], s_last[2][W];
    __shared__ float s_spb[W], s_spnb[W];
    __shared__ unsigned long long s_top[W][W];
    __shared__ unsigned short s_bp[T][W];                 // (parent<<8)|sym, 0xFF = stay
    __shared__ int   s_selslot[P], s_sellen[P];
    __shared__ float s_selscore[P];

    if (tid < W) {
        s_pb[0][tid]   = (tid == 0) ? 0.0f : NEGF;
        s_pnb[0][tid]  = NEGF;
        s_ln[0][tid]   = 0;
        s_last[0][tid] = -1;
    }
    if (tid < C) sh_lp[0][tid] = data[(size_t)b * C + tid];
    if (tid >= C && tid < C + S) sh_srt[0][tid - C] = g_sorted[((size_t)b * T) * S + (tid - C)];
    __syncthreads();

    for (int t = 0; t < len; ++t) {
        const int buf = t & 1;

        // prefetch next timestep
        float pre = 0.0f;
        unsigned long long pres = 0ULL;
        if (t + 1 < T) {
            if (tid < C) pre = data[(size_t)((t + 1) * B + b) * C + tid];
            else if (tid < C + S) pres = g_sorted[((size_t)b * T + (t + 1)) * S + (tid - C)];
        }

        // -------- phase 1: warp w builds & sorts its 21 candidates --------
        {
            const int w  = wid;
            float pbw    = s_pb[buf][w];
            float pnbw   = s_pnb[buf][w];
            int   lw     = s_ln[buf][w];
            int   lastw  = s_last[buf][w];
            float ptot   = lae(pbw, pnbw);
            float spb    = ptot + sh_lp[buf][0];
            int   li     = (lw > 0) ? lastw : 0;
            float spnb   = (lw > 0) ? (pnbw + sh_lp[buf][li]) : NEGF;
            if (lane == 0) { s_spb[w] = spb; s_spnb[w] = spnb; }
            float sstay  = lae(spb, spnb);

            unsigned long long key = 0ULL;
            if (lane < S) {
                unsigned long long sk = sh_srt[buf][lane];
                int   c   = 127 - (int)(sk & 127ULL);
                float lpc = funord((unsigned)(sk >> 7));
                float sc  = lpc + ((c == lastw) ? pbw : ptot);
                key = make_key(sc, W + w * C + c);
            } else if (lane == S) {
                key = make_key(sstay, w);
            }

            // bitonic sort 32, descending
            #pragma unroll
            for (int k2 = 2; k2 <= 32; k2 <<= 1) {
                #pragma unroll
                for (int j = k2 >> 1; j > 0; j >>= 1) {
                    unsigned long long o = __shfl_xor_sync(0xffffffffu, key, j);
                    bool takemax = ((lane & k2) == 0) == ((lane & j) == 0);
                    bool bigger  = key > o;
                    key = (takemax == bigger) ? key : o;
                }
            }
            if (lane < W) s_top[w][lane] = key;
        }
        __syncthreads();

        // -------- phase 2: warp 0 bitonic-merges 16 sorted 16-lists --------
        if (wid == 0) {
            unsigned long long m[8];
            const int rr = lane & 15;
            const int h  = lane >> 4;
            #pragma unroll
            for (int q = 0; q < 8; ++q) m[q] = s_top[2 * q + h][rr];

            #pragma unroll
            for (int lvl = 0; lvl < 4; ++lvl) {
                const int nreg = 8 >> lvl;
                #pragma unroll
                for (int q = 0; q < 8; ++q) {
                    if (q >= nreg) break;
                    // top-16 of two sorted desc lists: max(a[i], b[15-i]) via lane^31
                    unsigned long long o = __shfl_xor_sync(0xffffffffu, m[q], 31);
                    unsigned long long v = (m[q] > o) ? m[q] : o;   // bitonic in each half
                    #pragma unroll
                    for (int j = 8; j > 0; j >>= 1) {               // clean -> sorted desc
                        unsigned long long o2 = __shfl_xor_sync(0xffffffffu, v, j);
                        bool takemax = ((lane & j) == 0);
                        bool bigger  = v > o2;
                        v = (takemax == bigger) ? v : o2;
                    }
                    m[q] = v;   // sorted desc in lanes 0-15, mirrored copy in 16-31
                }
                // repack: list pair (2q,2q+1) -> halves of reg q (mirror copy is free)
                #pragma unroll
                for (int q = 0; q < 4; ++q) {
                    if (q >= (nreg >> 1)) break;
                    m[q] = (lane < 16) ? m[2 * q] : m[2 * q + 1];
                }
            }

            if (lane < W) {
                unsigned long long mywin = m[0];       // rank-`lane` global winner
                int   idx   = key_idx(mywin);
                float score = key_score(mywin);
                int parent, sym, nlen, nlast;
                float npb, npnb;
                if (idx < W) {                          // stay
                    parent = idx; sym = 0xFF;
                    npb   = s_spb[parent];
                    npnb  = s_spnb[parent];
                    nlen  = s_ln[buf][parent];
                    nlast = s_last[buf][parent];
                } else {                                // extend with symbol c
                    int e  = idx - W;
                    parent = e / C;
                    int c  = e - parent * C;
                    sym   = c;
                    npb   = NEGF;
                    npnb  = score;
                    nlen  = s_ln[buf][parent] + 1;
                    nlast = c;
                }
                const int nb = buf ^ 1;
                s_pb[nb][lane]   = npb;
                s_pnb[nb][lane]  = npnb;
                s_ln[nb][lane]   = nlen;
                s_last[nb][lane] = nlast;
                s_bp[t][lane]    = (unsigned short)((parent << 8) | sym);
            }
        }
        // park prefetched rows
        if (t + 1 < T) {
            if (tid < C) sh_lp[buf ^ 1][tid] = pre;
            else if (tid < C + S) sh_srt[buf ^ 1][tid - C] = pres;
        }
        __syncthreads();
    }

    // -------- final top-P over total beam probabilities --------
    if (wid == 0) {
        const int cb = len & 1;
        unsigned long long key = 0ULL;
        if (lane < W)
            key = make_key(lae(s_pb[cb][lane], s_pnb[cb][lane]), lane);
        #pragma unroll
        for (int r = 0; r < P; ++r) {
            unsigned long long win = warp_max(key);
            if (key == win) key = 0ULL;
            if (lane == 0) {
                int slot      = key_idx(win);
                s_selslot[r]  = slot;
                s_selscore[r] = key_score(win);
                s_sellen[r]   = s_ln[cb][slot];
            }
        }
    }
    __syncthreads();

    // -------- outputs (flattened float32): -scores, lens, labels --------
    float* o_neg = out;
    float* o_len = out + B * P;
    float* o_dec = out + 2 * B * P;

    if (tid < P) {
        o_neg[b * P + tid] = -s_selscore[tid];
        o_len[b * P + tid] = (float)s_sellen[tid];
    }
    for (int i = tid; i < P * T; i += blockDim.x)
        o_dec[(size_t)b * P * T + i] = -1.0f;
    __syncthreads();

    if (tid < P) {
        int slot = s_selslot[tid];
        int pos  = s_sellen[tid];
        float* dst = o_dec + ((size_t)b * P + tid) * T;
        for (int tt = len - 1; tt >= 0; --tt) {
            unsigned e = s_bp[tt][slot];
            int sym = e & 0xFF;
            slot    = e >> 8;
            if (sym != 0xFF) dst[--pos] = (float)sym;
        }
    }
}

extern "C" void kernel_launch(void* const* d_in, const int* in_sizes, int n_in,
                              void* d_out, int out_size) {
    const float* data = (const float*)d_in[0];
    const int*   dlen = (const int*)d_in[1];
    presort_kernel<<<(B * T + 7) / 8, 256>>>(data);
    ctc_beam_kernel<<<B, 512>>>(data, dlen, (float*)d_out);
}

// round 5
// speedup vs baseline: 1.1851x; 1.1851x over previous
#include <cuda_runtime.h>
#include <stdint.h>

#define NEGF (-1e30f)

constexpr int T = 1024;
constexpr int B = 32;
constexpr int C = 96;
constexpr int W = 16;   // beam width
constexpr int P = 4;    // top paths
constexpr int S = 17;   // top lp columns kept per (b,t): >=16 non-demoted => exact

// per (b,t): top-S non-blank lp columns as packed keys (ord(lp)<<7 | (127-c)), desc
__device__ unsigned long long g_sorted[(size_t)B * T * S];

// ---------- key helpers ----------
__device__ __forceinline__ unsigned ford(float f) {
    unsigned u = __float_as_uint(f);
    return (u & 0x80000000u) ? ~u : (u | 0x80000000u);
}
__device__ __forceinline__ float funord(unsigned ord) {
    unsigned u = (ord & 0x80000000u) ? (ord ^ 0x80000000u) : ~ord;
    return __uint_as_float(u);
}
// larger score wins; ties -> lower global index wins (matches jax.lax.top_k)
__device__ __forceinline__ unsigned long long make_key(float f, int idx) {
    return ((unsigned long long)ford(f) << 11) | (unsigned long long)(2047 - idx);
}
__device__ __forceinline__ int key_idx(unsigned long long k) { return 2047 - (int)(k & 2047ULL); }
__device__ __forceinline__ float key_score(unsigned long long k) { return funord((unsigned)(k >> 11)); }

__device__ __forceinline__ float lae(float a, float b) {   // jnp.logaddexp
    float m = fmaxf(a, b);
    float d = fabsf(a - b);
    return m + log1pf(expf(-d));
}
__device__ __forceinline__ unsigned long long warp_max(unsigned long long v) {
    #pragma unroll
    for (int o = 16; o; o >>= 1) {
        unsigned long long w = __shfl_xor_sync(0xffffffffu, v, o);
        v = (w > v) ? w : v;
    }
    return v;
}

// ============================================================================
// Kernel 1: per-(b,t) bitonic sort of non-blank lp columns, keep top-S.
// ============================================================================
__global__ __launch_bounds__(256)
void presort_kernel(const float* __restrict__ data)   // [T, B, C]
{
    int warp = (blockIdx.x * blockDim.x + threadIdx.x) >> 5;
    if (warp >= B * T) return;
    int b = warp / T, t = warp - b * T;
    int lane = threadIdx.x & 31;

    const float* row = data + ((size_t)t * B + b) * C;
    unsigned long long k[4];
    #pragma unroll
    for (int r = 0; r < 4; ++r) {
        int c = r * 32 + lane;
        if (c >= 1 && c < C)
            k[r] = ((unsigned long long)ford(row[c]) << 7) | (unsigned long long)(127 - c);
        else
            k[r] = 0ULL;
    }
    #pragma unroll
    for (int k2 = 2; k2 <= 128; k2 <<= 1) {
        #pragma unroll
        for (int j = 64; j > 0; j >>= 1) {
            if (j >= k2) continue;
            if (j >= 32) {
                int rj = j >> 5;
                #pragma unroll
                for (int r = 0; r < 4; ++r) {
                    if ((r & rj) == 0) {
                        int pr = r | rj;
                        bool desc = (((r * 32) & k2) == 0);
                        unsigned long long a = k[r], c2 = k[pr];
                        unsigned long long mx = a > c2 ? a : c2;
                        unsigned long long mn = a > c2 ? c2 : a;
                        k[r]  = desc ? mx : mn;
                        k[pr] = desc ? mn : mx;
                    }
                }
            } else {
                #pragma unroll
                for (int r = 0; r < 4; ++r) {
                    unsigned long long o = __shfl_xor_sync(0xffffffffu, k[r], j);
                    int e = r * 32 + lane;
                    bool takemax = ((e & k2) == 0) == ((lane & j) == 0);
                    bool bigger  = k[r] > o;
                    k[r] = (takemax == bigger) ? k[r] : o;
                }
            }
        }
    }
    if (lane < S)
        g_sorted[((size_t)b * T + t) * S + lane] = k[0];
}

// ============================================================================
// Kernel 2: sequential beam search. Phase1: ballot-rank insertion (no sort).
// Warp 0: bitonic merge + register-resident state update (one lae per beam).
// ============================================================================
__global__ __launch_bounds__(512, 1)
void ctc_beam_kernel(const float* __restrict__ data,      // [T, B, C]
                     const int*   __restrict__ data_len,  // [B]
                     float*       __restrict__ out)
{
    const int b    = blockIdx.x;
    const int tid  = threadIdx.x;
    const int lane = tid & 31;
    const int wid  = tid >> 5;
    const int len  = data_len[b];
    const unsigned FULL = 0xffffffffu;

    __shared__ float sh_lp[2][C];
    __shared__ unsigned long long sh_srt[2][S];
    __shared__ float sf_ptot[W];
    __shared__ int   sf_last[W];
    __shared__ unsigned long long sf_stay[W], sf_rep[W];
    __shared__ unsigned long long s_top[W][W];
    __shared__ unsigned short s_bp[T][W];                 // (parent<<8)|sym, 0xFF = stay
    __shared__ int   s_selslot[P], s_sellen[P];
    __shared__ float s_selscore[P];

    if (tid < C) sh_lp[0][tid] = data[(size_t)b * C + tid];
    else if (tid < C + S) sh_srt[0][tid - C] = g_sorted[((size_t)b * T) * S + (tid - C)];
    __syncthreads();

    // warp-0 register state: lane = beam slot
    float spb_r = NEGF, spnb_r = NEGF, ptot_r = NEGF;
    int   len_r = 0, last_r = -1;

    if (wid == 0) {
        float pb0 = (lane == 0) ? 0.0f : NEGF;
        ptot_r = lae(pb0, NEGF);
        spb_r  = ptot_r + sh_lp[0][0];
        spnb_r = NEGF;
        float sstay = lae(spb_r, spnb_r);
        if (lane < W) {
            sf_ptot[lane] = ptot_r;
            sf_last[lane] = -1;
            sf_stay[lane] = make_key(sstay, lane);
            sf_rep[lane]  = 0ULL;
        }
    }
    __syncthreads();

    for (int t = 0; t < len; ++t) {
        const int buf = t & 1, nb = buf ^ 1;

        // prefetch next timestep into registers
        float pre = 0.0f; unsigned long long pres = 0ULL;
        if (t + 1 < T) {
            if (tid < C) pre = data[(size_t)((t + 1) * B + b) * C + tid];
            else if (tid < C + S) pres = g_sorted[((size_t)b * T + (t + 1)) * S + (tid - C)];
        }

        // -------- phase 1: warp w emits its sorted top-16 (no sort) --------
        {
            const int w = wid;
            float ptw  = sf_ptot[w];
            int   lastw = sf_last[w];
            unsigned long long stayk = sf_stay[w];
            unsigned long long repk  = sf_rep[w];

            unsigned long long key = 0ULL; int c = -2;
            if (lane < S) {
                unsigned long long sk = sh_srt[buf][lane];
                c = 127 - (int)(sk & 127ULL);
                float lpc = funord((unsigned)(sk >> 7));
                key = make_key(lpc + ptw, W + w * C + c);  // monotone shift: stays sorted
            }
            // odd-even cleanup pass A: pairs (0,1),(2,3),...
            {
                unsigned long long ok = __shfl_xor_sync(FULL, key, 1);
                int oc = __shfl_xor_sync(FULL, c, 1);
                bool keep_hi = (lane & 1) == 0;
                if (lane < S && (keep_hi != (key > ok))) { key = ok; c = oc; }
            }
            // pass B: pairs (1,2),(3,4),...,(15,16)
            {
                int partner = (lane == 0) ? 0 : (lane + ((lane & 1) ? 1 : -1));
                unsigned long long ok = __shfl_sync(FULL, key, partner);
                int oc = __shfl_sync(FULL, c, partner);
                bool keep_hi = (lane & 1) == 1;
                if (lane >= 1 && lane < S && (keep_hi != (key > ok))) { key = ok; c = oc; }
            }
            // drop the (undemoted) c==last cell; rank-insert repk & stayk
            unsigned pm = __ballot_sync(FULL, (lane < S) && (c == lastw));
            bool matched = pm != 0u;
            int  p0 = __ffs(pm) - 1;
            bool is_stat = (lane < S) && !(matched && lane == p0);
            unsigned gb_rep  = __ballot_sync(FULL, is_stat && (key > repk));
            unsigned gb_stay = __ballot_sync(FULL, is_stat && (key > stayk));
            if (is_stat) {
                int r = lane - ((matched && lane > p0) ? 1 : 0)
                      + ((repk  > key) ? 1 : 0) + ((stayk > key) ? 1 : 0);
                if (r < W) s_top[w][r] = key;
            }
            if (lane == 0) {
                int rr2 = __popc(gb_rep)  + ((stayk > repk)  ? 1 : 0);
                int rs  = __popc(gb_stay) + ((repk  > stayk) ? 1 : 0);
                if (rr2 < W) s_top[w][rr2] = repk;
                if (rs  < W) s_top[w][rs]  = stayk;
            }
        }
        // park prefetched rows BEFORE barrier (warp0 update reads sh_lp[nb])
        if (t + 1 < T) {
            if (tid < C) sh_lp[nb][tid] = pre;
            else if (tid < C + S) sh_srt[nb][tid - C] = pres;
        }
        __syncthreads();

        // -------- warp 0: merge 16 sorted 16-lists + state update --------
        if (wid == 0) {
            unsigned long long m[8];
            const int rr = lane & 15, h = lane >> 4;
            #pragma unroll
            for (int q = 0; q < 8; ++q) m[q] = s_top[2 * q + h][rr];
            #pragma unroll
            for (int lvl = 0; lvl < 4; ++lvl) {
                const int nreg = 8 >> lvl;
                #pragma unroll
                for (int q = 0; q < 8; ++q) {
                    if (q >= nreg) break;
                    unsigned long long o = __shfl_xor_sync(FULL, m[q], 31);
                    unsigned long long v = (m[q] > o) ? m[q] : o;
                    #pragma unroll
                    for (int j = 8; j > 0; j >>= 1) {
                        unsigned long long o2 = __shfl_xor_sync(FULL, v, j);
                        bool takemax = ((lane & j) == 0);
                        bool bigger  = v > o2;
                        v = (takemax == bigger) ? v : o2;
                    }
                    m[q] = v;
                }
                #pragma unroll
                for (int q = 0; q < 4; ++q) {
                    if (q >= (nreg >> 1)) break;
                    m[q] = (lane < 16) ? m[2 * q] : m[2 * q + 1];
                }
            }

            unsigned long long win = m[0];           // lane r (0-15): rank-r winner
            int   idx   = key_idx(win);
            float score = key_score(win);
            bool  is_stay = idx < W;
            int   e = is_stay ? 0 : (idx - W);
            int   epar = e / C;
            int   csym = e - epar * C;
            int   parent = (is_stay ? idx : epar) & 31;
            float p_spb  = __shfl_sync(FULL, spb_r,  parent);
            float p_spnb = __shfl_sync(FULL, spnb_r, parent);
            int   p_len  = __shfl_sync(FULL, len_r,  parent);
            int   p_last = __shfl_sync(FULL, last_r, parent);

            float npb   = is_stay ? p_spb  : NEGF;
            float npnb  = is_stay ? p_spnb : score;
            int   nlen  = is_stay ? p_len  : (p_len + 1);
            int   nlast = is_stay ? p_last : csym;
            float nptot = score;                     // == lae(npb, npnb) bit-exactly

            float lp0 = sh_lp[nb][0];
            int   li  = (nlast >= 0) ? nlast : 0;
            float lpl = sh_lp[nb][li];
            float nspb  = nptot + lp0;
            float nspnb = (nlen > 0) ? (npnb + lpl) : NEGF;
            float nstay = lae(nspb, nspnb);          // the one lae on the hot path

            spb_r = nspb; spnb_r = nspnb; ptot_r = nptot;
            len_r = nlen; last_r = nlast;

            if (lane < W) {
                sf_ptot[lane] = nptot;
                sf_last[lane] = nlast;
                sf_stay[lane] = make_key(nstay, lane);
                sf_rep[lane]  = (nlen > 0) ? make_key(npb + lpl, W + lane * C + nlast)
                                           : 0ULL;
                s_bp[t][lane] = (unsigned short)((parent << 8) | (is_stay ? 0xFF : csym));
            }
        }
        __syncthreads();
    }

    // -------- final top-P over total beam probabilities --------
    if (wid == 0) {
        unsigned long long key = (lane < W) ? make_key(ptot_r, lane) : 0ULL;
        #pragma unroll
        for (int r = 0; r < P; ++r) {
            unsigned long long win = warp_max(key);
            if (key == win) key = 0ULL;
            int slot = key_idx(win) & 31;
            int sl = __shfl_sync(FULL, len_r, slot);
            if (lane == 0) {
                s_selslot[r]  = slot;
                s_selscore[r] = key_score(win);
                s_sellen[r]   = sl;
            }
        }
    }
    __syncthreads();

    // -------- outputs (flattened float32): -scores, lens, labels --------
    float* o_neg = out;
    float* o_len = out + B * P;
    float* o_dec = out + 2 * B * P;

    if (tid < P) {
        o_neg[b * P + tid] = -s_selscore[tid];
        o_len[b * P + tid] = (float)s_sellen[tid];
    }
    for (int i = tid; i < P * T; i += blockDim.x)
        o_dec[(size_t)b * P * T + i] = -1.0f;
    __syncthreads();

    if (tid < P) {
        int slot = s_selslot[tid];
        int pos  = s_sellen[tid];
        float* dst = o_dec + ((size_t)b * P + tid) * T;
        for (int tt = len - 1; tt >= 0; --tt) {
            unsigned e = s_bp[tt][slot];
            int sym = e & 0xFF;
            slot    = e >> 8;
            if (sym != 0xFF) dst[--pos] = (float)sym;
        }
    }
}

extern "C" void kernel_launch(void* const* d_in, const int* in_sizes, int n_in,
                              void* d_out, int out_size) {
    const float* data = (const float*)d_in[0];
    const int*   dlen = (const int*)d_in[1];
    presort_kernel<<<(B * T + 7) / 8, 256>>>(data);
    ctc_beam_kernel<<<B, 512>>>(data, dlen, (float*)d_out);
}